// round 2
// baseline (speedup 1.0000x reference)
#include <cuda_runtime.h>
#include <math.h>
#include <stdint.h>

// Problem constants
#define BATCH   4
#define CH      64
#define HPX     64
#define WPX     64
#define NTOK    4096          // tokens per batch (64x64)
#define TOKALL  16384         // BATCH * NTOK
#define ATT_SCALE 0.125f      // (C)^-0.5

#define BUF_FLOATS 1048576    // TOKALL * CH

// 17 scratch buffers of [TOKALL][CH] floats (~68 MB) + gap
__device__ float g_scratch[17 * BUF_FLOATS];
__device__ float g_gap[BATCH * CH];

__device__ __forceinline__ float gelu_exact(float x) {
    return 0.5f * x * (1.0f + erff(x * 0.70710678118654752440f));
}

// ---------------------------------------------------------------------------
// avgpool 2x2: x [B,C,128,128] -> xp tokens [B, N, C]  (token = h*64+w)
// grid: B*HPX blocks, 256 threads
// ---------------------------------------------------------------------------
__global__ void avgpool_kernel(const float* __restrict__ x, float* __restrict__ xp) {
    int b  = blockIdx.x >> 6;
    int hp = blockIdx.x & 63;
    const float* xb = x + (size_t)b * CH * 128 * 128;
    float* xpb = xp + ((size_t)b * NTOK + (size_t)hp * 64) * CH;
    for (int idx = threadIdx.x; idx < 64 * CH; idx += blockDim.x) {
        int c  = idx & 63;
        int wp = idx >> 6;
        const float* p = xb + ((size_t)c * 128 + 2 * hp) * 128 + 2 * wp;
        float v = 0.25f * (p[0] + p[1] + p[128] + p[129]);
        xpb[(size_t)wp * CH + c] = v;
    }
}

// ---------------------------------------------------------------------------
// gap[b,c] = mean over H,W of x[b,c]  (mean of x == mean of avgpool(x))
// grid: B*CH blocks, 256 threads
// ---------------------------------------------------------------------------
__global__ void gap_kernel(const float* __restrict__ x, float* __restrict__ gap) {
    int bc = blockIdx.x;
    const float* p = x + (size_t)bc * 16384;
    float s = 0.f;
    for (int i = threadIdx.x; i < 16384; i += 256) s += p[i];
    __shared__ float red[256];
    red[threadIdx.x] = s;
    __syncthreads();
    for (int st = 128; st > 0; st >>= 1) {
        if (threadIdx.x < st) red[threadIdx.x] += red[threadIdx.x + st];
        __syncthreads();
    }
    if (threadIdx.x == 0) gap[bc] = red[0] * (1.0f / 16384.0f);
}

// ---------------------------------------------------------------------------
// Generic 64x64 linear over tokens:
//   out[t, o] = sum_ci W[o][ci] * xin(t,ci) + bias[o]   (+ res[t,o] if res)
//   xin(t,ci) = (in0 + in1)[t,ci] * (gapv ? gap[b,ci] : 1)
// 128 threads = 128 tokens per block; grid 128 blocks.
// W cached transposed in smem -> broadcast float4 loads, FMA-bound.
// ---------------------------------------------------------------------------
__global__ void linear_kernel(const float* __restrict__ in0,
                              const float* __restrict__ in1,
                              const float* __restrict__ gapv,
                              const float* __restrict__ W,
                              const float* __restrict__ bias,
                              const float* __restrict__ res,
                              float* __restrict__ out) {
    __shared__ __align__(16) float Wt[64 * 68];   // Wt[ci*68 + o] = W[o*64+ci]
    __shared__ float xs[128 * 17];
    int tid = threadIdx.x;
    for (int idx = tid; idx < 4096; idx += 128) {
        int o = idx >> 6, ci = idx & 63;
        Wt[ci * 68 + o] = W[idx];
    }
    int t0 = blockIdx.x * 128;
    int g  = t0 + tid;               // global token
    float acc[64];
#pragma unroll
    for (int o = 0; o < 64; o++) acc[o] = bias[o];

    size_t base = (size_t)g * 64;
    for (int ci0 = 0; ci0 < 64; ci0 += 16) {
        __syncthreads();
        for (int idx = tid; idx < 128 * 16; idx += 128) {
            int t  = idx >> 4;
            int cc = idx & 15;
            int ci = ci0 + cc;
            size_t ga = ((size_t)(t0 + t)) * 64 + ci;
            float v = in0[ga];
            if (in1)  v += in1[ga];
            if (gapv) v *= gapv[(size_t)((t0 + t) >> 12) * 64 + ci];
            xs[t * 17 + cc] = v;
        }
        __syncthreads();
#pragma unroll
        for (int cc = 0; cc < 16; cc++) {
            float xv = xs[tid * 17 + cc];
            const float4* wrow = reinterpret_cast<const float4*>(&Wt[(ci0 + cc) * 68]);
#pragma unroll
            for (int o4 = 0; o4 < 16; o4++) {
                float4 w = wrow[o4];
                acc[o4 * 4 + 0] += xv * w.x;
                acc[o4 * 4 + 1] += xv * w.y;
                acc[o4 * 4 + 2] += xv * w.z;
                acc[o4 * 4 + 3] += xv * w.w;
            }
        }
    }
    if (res) {
#pragma unroll
        for (int o = 0; o < 64; o++) acc[o] += res[base + o];
    }
#pragma unroll
    for (int o4 = 0; o4 < 16; o4++) {
        float4 v = make_float4(acc[o4 * 4 + 0], acc[o4 * 4 + 1],
                               acc[o4 * 4 + 2], acc[o4 * 4 + 3]);
        reinterpret_cast<float4*>(out + base)[o4] = v;
    }
}

// ---------------------------------------------------------------------------
// Depthwise 5-tap strip conv (+ bias + exact GELU), zero pad 2.
// vertical=1: taps along h; vertical=0: taps along w.
// grid: TOKALL*CH/256 blocks, 256 threads; c fastest (coalesced).
// ---------------------------------------------------------------------------
__global__ void dwconv5_kernel(const float* __restrict__ in,
                               const float* __restrict__ wt,
                               const float* __restrict__ bias,
                               float* __restrict__ out, int vertical) {
    int idx = blockIdx.x * 256 + threadIdx.x;
    int c = idx & 63;
    int g = idx >> 6;
    int b = g >> 12;
    int n = g & 4095;
    int h = n >> 6, w = n & 63;
    float acc = bias[c];
#pragma unroll
    for (int d = -2; d <= 2; d++) {
        int hh = h, ww = w;
        if (vertical) hh = h + d; else ww = w + d;
        if (hh >= 0 && hh < 64 && ww >= 0 && ww < 64) {
            size_t src = (((size_t)b << 12) | ((size_t)hh << 6) | (size_t)ww) * 64 + c;
            acc += wt[c * 5 + d + 2] * in[src];
        }
    }
    out[(size_t)g * 64 + c] = gelu_exact(acc);
}

// ---------------------------------------------------------------------------
// Depthwise 3x3 conv (+ bias + exact GELU), zero pad 1.
// ---------------------------------------------------------------------------
__global__ void dwconv3x3_kernel(const float* __restrict__ in,
                                 const float* __restrict__ wt,
                                 const float* __restrict__ bias,
                                 float* __restrict__ out) {
    int idx = blockIdx.x * 256 + threadIdx.x;
    int c = idx & 63;
    int g = idx >> 6;
    int b = g >> 12;
    int n = g & 4095;
    int h = n >> 6, w = n & 63;
    float acc = bias[c];
#pragma unroll
    for (int ky = 0; ky < 3; ky++) {
#pragma unroll
        for (int kx = 0; kx < 3; kx++) {
            int hh = h + ky - 1, ww = w + kx - 1;
            if (hh >= 0 && hh < 64 && ww >= 0 && ww < 64) {
                size_t src = (((size_t)b << 12) | ((size_t)hh << 6) | (size_t)ww) * 64 + c;
                acc += wt[c * 9 + ky * 3 + kx] * in[src];
            }
        }
    }
    out[(size_t)g * 64 + c] = gelu_exact(acc);
}

// ---------------------------------------------------------------------------
// Flash attention, fp32. Q,K,V,O: [B, N, C] with N=4096, C=64.
// grid (N/64, B), 256 threads (16x16), 4x4 register tiles, online softmax.
// dyn smem: Qs[64][64] + Ks[64][65] + Vs[64][64] + Ps[64][64] = 65792 B.
// ---------------------------------------------------------------------------
__global__ void attn_kernel(const float* __restrict__ Q, const float* __restrict__ K,
                            const float* __restrict__ V, float* __restrict__ O) {
    extern __shared__ __align__(16) float sm[];
    float* Qs = sm;              // [i][c]  pitch 64
    float* Ks = sm + 4096;       // [j][c]  pitch 65 (avoids 16-way conflicts)
    float* Vs = Ks + 64 * 65;    // [j][c]  pitch 64
    float* Ps = Vs + 4096;       // [i][j]  pitch 64

    int b  = blockIdx.y;
    int qt = blockIdx.x;
    const float* Qb = Q + ((size_t)b * NTOK + (size_t)qt * 64) * 64;
    const float* Kb = K + (size_t)b * NTOK * 64;
    const float* Vb = V + (size_t)b * NTOK * 64;
    float* Ob = O + ((size_t)b * NTOK + (size_t)qt * 64) * 64;

    int tid = threadIdx.x;
    int tx = tid & 15, ty = tid >> 4;
    int i0 = ty * 4, j0 = tx * 4;

    for (int idx = tid; idx < 4096; idx += 256) Qs[idx] = Qb[idx];

    float m[4], l[4], o[4][4];
#pragma unroll
    for (int ii = 0; ii < 4; ii++) {
        m[ii] = -1e30f; l[ii] = 0.f;
#pragma unroll
        for (int jj = 0; jj < 4; jj++) o[ii][jj] = 0.f;
    }

    for (int kt = 0; kt < 64; kt++) {
        __syncthreads();   // protect Ks/Vs from previous iteration's readers
        const float* Kt = Kb + (size_t)kt * 64 * 64;
        const float* Vt = Vb + (size_t)kt * 64 * 64;
        for (int idx = tid; idx < 4096; idx += 256) {
            int j = idx >> 6, c2 = idx & 63;
            Ks[j * 65 + c2] = Kt[idx];
            Vs[idx] = Vt[idx];
        }
        __syncthreads();

        // S = Q K^T * scale
        float s[4][4];
#pragma unroll
        for (int ii = 0; ii < 4; ii++)
#pragma unroll
            for (int jj = 0; jj < 4; jj++) s[ii][jj] = 0.f;

        for (int c2 = 0; c2 < 64; c2++) {
            float a[4], bb[4];
#pragma unroll
            for (int ii = 0; ii < 4; ii++) a[ii] = Qs[(i0 + ii) * 64 + c2];
#pragma unroll
            for (int jj = 0; jj < 4; jj++) bb[jj] = Ks[(j0 + jj) * 65 + c2];
#pragma unroll
            for (int ii = 0; ii < 4; ii++)
#pragma unroll
                for (int jj = 0; jj < 4; jj++) s[ii][jj] += a[ii] * bb[jj];
        }

        // online softmax update (row reduce over 16 lanes in the tx group)
#pragma unroll
        for (int ii = 0; ii < 4; ii++) {
#pragma unroll
            for (int jj = 0; jj < 4; jj++) s[ii][jj] *= ATT_SCALE;
            float rm = fmaxf(fmaxf(s[ii][0], s[ii][1]), fmaxf(s[ii][2], s[ii][3]));
#pragma unroll
            for (int d = 8; d > 0; d >>= 1)
                rm = fmaxf(rm, __shfl_xor_sync(0xffffffffu, rm, d, 16));
            float mn = fmaxf(m[ii], rm);
            float sf = __expf(m[ii] - mn);
            float rs = 0.f;
#pragma unroll
            for (int jj = 0; jj < 4; jj++) {
                float pv = __expf(s[ii][jj] - mn);
                s[ii][jj] = pv;
                rs += pv;
            }
#pragma unroll
            for (int d = 8; d > 0; d >>= 1)
                rs += __shfl_xor_sync(0xffffffffu, rs, d, 16);
            l[ii] = l[ii] * sf + rs;
            m[ii] = mn;
#pragma unroll
            for (int jj = 0; jj < 4; jj++) o[ii][jj] *= sf;
            *reinterpret_cast<float4*>(&Ps[(i0 + ii) * 64 + j0]) =
                make_float4(s[ii][0], s[ii][1], s[ii][2], s[ii][3]);
        }
        __syncthreads();

        // O += P @ V
        for (int j = 0; j < 64; j++) {
            float a[4];
#pragma unroll
            for (int ii = 0; ii < 4; ii++) a[ii] = Ps[(i0 + ii) * 64 + j];
            float4 bv = *reinterpret_cast<const float4*>(&Vs[j * 64 + j0]);
#pragma unroll
            for (int ii = 0; ii < 4; ii++) {
                o[ii][0] += a[ii] * bv.x;
                o[ii][1] += a[ii] * bv.y;
                o[ii][2] += a[ii] * bv.z;
                o[ii][3] += a[ii] * bv.w;
            }
        }
    }

#pragma unroll
    for (int ii = 0; ii < 4; ii++) {
        float inv = 1.0f / l[ii];
        *reinterpret_cast<float4*>(&Ob[(i0 + ii) * 64 + j0]) =
            make_float4(o[ii][0] * inv, o[ii][1] * inv, o[ii][2] * inv, o[ii][3] * inv);
    }
}

// ---------------------------------------------------------------------------
// LayerNorm over C=64 per token. warp per token; grid TOKALL/8, 256 threads.
// ---------------------------------------------------------------------------
__global__ void layernorm_kernel(const float* __restrict__ in,
                                 const float* __restrict__ gw,
                                 const float* __restrict__ bw,
                                 float* __restrict__ out) {
    int warp = threadIdx.x >> 5, lane = threadIdx.x & 31;
    int tok = blockIdx.x * 8 + warp;
    const float* p = in + (size_t)tok * 64;
    float v0 = p[lane], v1 = p[lane + 32];
    float s = v0 + v1;
#pragma unroll
    for (int d = 16; d > 0; d >>= 1) s += __shfl_xor_sync(0xffffffffu, s, d);
    float mu = s * (1.0f / 64.0f);
    float d0 = v0 - mu, d1 = v1 - mu;
    float q = d0 * d0 + d1 * d1;
#pragma unroll
    for (int d = 16; d > 0; d >>= 1) q += __shfl_xor_sync(0xffffffffu, q, d);
    float rstd = rsqrtf(q * (1.0f / 64.0f) + 1e-5f);
    float* po = out + (size_t)tok * 64;
    po[lane]      = d0 * rstd * gw[lane]      + bw[lane];
    po[lane + 32] = d1 * rstd * gw[lane + 32] + bw[lane + 32];
}

// ---------------------------------------------------------------------------
// Bilinear x2 upsample, align_corners=True. in tokens [B,N,C] -> out [B,C,128,128]
// block: 4 pixels x 64 channels; grid B*128*128/4.
// ---------------------------------------------------------------------------
__global__ void upsample_kernel(const float* __restrict__ in, float* __restrict__ out) {
    int tid = threadIdx.x;
    int c = tid & 63;
    int p = blockIdx.x * 4 + (tid >> 6);
    int b = p >> 14;
    int rem = p & 16383;
    int y = rem >> 7, x = rem & 127;
    float sy = (float)y * (63.0f / 127.0f);
    int y0 = (int)sy; float wy = sy - (float)y0; int y1 = min(y0 + 1, 63);
    float sx = (float)x * (63.0f / 127.0f);
    int x0 = (int)sx; float wx = sx - (float)x0; int x1 = min(x0 + 1, 63);
    const float* base = in + (size_t)b * NTOK * 64;
    float v00 = base[((size_t)y0 * 64 + x0) * 64 + c];
    float v01 = base[((size_t)y0 * 64 + x1) * 64 + c];
    float v10 = base[((size_t)y1 * 64 + x0) * 64 + c];
    float v11 = base[((size_t)y1 * 64 + x1) * 64 + c];
    float r0 = v00 * (1.0f - wx) + v01 * wx;
    float r1 = v10 * (1.0f - wx) + v11 * wx;
    out[(((size_t)b * 64 + c) * 128 + y) * 128 + x] = r0 * (1.0f - wy) + r1 * wy;
}

// ---------------------------------------------------------------------------
// Host orchestration
// ---------------------------------------------------------------------------
extern "C" void kernel_launch(void* const* d_in, const int* in_sizes, int n_in,
                              void* d_out, int out_size) {
    const float* x       = (const float*)d_in[0];
    const float* Wq      = (const float*)d_in[1];
    const float* bq      = (const float*)d_in[2];
    const float* Wk      = (const float*)d_in[3];
    const float* bk      = (const float*)d_in[4];
    const float* Wv      = (const float*)d_in[5];
    const float* bv      = (const float*)d_in[6];
    const float* Wl      = (const float*)d_in[7];
    const float* bl      = (const float*)d_in[8];
    const float* Wo      = (const float*)d_in[9];
    const float* bo      = (const float*)d_in[10];
    const float* Wp      = (const float*)d_in[11];
    const float* bp      = (const float*)d_in[12];
    const float* sch_dw  = (const float*)d_in[13];
    const float* sch_dwb = (const float*)d_in[14];
    const float* sch_pw  = (const float*)d_in[15];
    const float* sch_pwb = (const float*)d_in[16];
    const float* scv_dw  = (const float*)d_in[17];
    const float* scv_dwb = (const float*)d_in[18];
    const float* scv_pw  = (const float*)d_in[19];
    const float* scv_pwb = (const float*)d_in[20];
    const float* convh_w = (const float*)d_in[21];
    const float* convh_b = (const float*)d_in[22];
    const float* dsc_dw  = (const float*)d_in[23];
    const float* dsc_dwb = (const float*)d_in[24];
    const float* dsc_pw  = (const float*)d_in[25];
    const float* dsc_pwb = (const float*)d_in[26];
    const float* ln_g    = (const float*)d_in[27];
    const float* ln_b    = (const float*)d_in[28];
    float* outp = (float*)d_out;

    float* S = nullptr; float* gap = nullptr;
    cudaGetSymbolAddress((void**)&S, g_scratch);
    cudaGetSymbolAddress((void**)&gap, g_gap);

    float* xp     = S + 0  * BUF_FLOATS;
    float* q      = S + 1  * BUF_FLOATS;
    float* k      = S + 2  * BUF_FLOATS;
    float* v      = S + 3  * BUF_FLOATS;
    float* xV     = S + 4  * BUF_FLOATS;
    float* attn1  = S + 5  * BUF_FLOATS;
    float* pl     = S + 6  * BUF_FLOATS;
    float* tA     = S + 7  * BUF_FLOATS;
    float* tB     = S + 8  * BUF_FLOATS;
    float* xh     = S + 9  * BUF_FLOATS;
    float* ph     = S + 10 * BUF_FLOATS;
    float* attn2  = S + 11 * BUF_FLOATS;
    float* prompt = S + 12 * BUF_FLOATS;
    float* pn     = S + 13 * BUF_FLOATS;
    float* dsco   = S + 14 * BUF_FLOATS;

    cudaFuncSetAttribute(attn_kernel, cudaFuncAttributeMaxDynamicSharedMemorySize, 65792);

    // 1. pooled tokens + GAP
    avgpool_kernel<<<BATCH * HPX, 256>>>(x, xp);
    gap_kernel<<<BATCH * CH, 256>>>(x, gap);

    // 2. q/k/v from gated tokens, x_V from plain tokens
    linear_kernel<<<128, 128>>>(xp, nullptr, gap, Wq, bq, nullptr, q);
    linear_kernel<<<128, 128>>>(xp, nullptr, gap, Wk, bk, nullptr, k);
    linear_kernel<<<128, 128>>>(xp, nullptr, gap, Wv, bv, nullptr, v);
    linear_kernel<<<128, 128>>>(xp, nullptr, nullptr, Wo, bo, nullptr, xV);

    // 3. self-attention -> prompt_l
    attn_kernel<<<dim3(NTOK / 64, BATCH), 256, 65792>>>(q, k, v, attn1);
    linear_kernel<<<128, 128>>>(attn1, nullptr, nullptr, Wl, bl, nullptr, pl);

    // 4. high-frequency branch
    dwconv5_kernel<<<TOKALL * CH / 256, 256>>>(xp, sch_dw, sch_dwb, tA, 1);   // 5x1 along h
    linear_kernel<<<128, 128>>>(tA, nullptr, nullptr, sch_pw, sch_pwb, nullptr, xh);
    dwconv5_kernel<<<TOKALL * CH / 256, 256>>>(xp, scv_dw, scv_dwb, tA, 0);   // 1x5 along w
    linear_kernel<<<128, 128>>>(tA, nullptr, nullptr, scv_pw, scv_pwb, nullptr, tB);
    linear_kernel<<<128, 128>>>(xh, tB, nullptr, convh_w, convh_b, nullptr, ph);

    // 5. cross-attention (Q=high, K=low, V=x_V) -> prompt
    attn_kernel<<<dim3(NTOK / 64, BATCH), 256, 65792>>>(ph, pl, xV, attn2);
    linear_kernel<<<128, 128>>>(attn2, nullptr, nullptr, Wp, bp, xV, prompt);

    // 6. LayerNorm over channels
    layernorm_kernel<<<TOKALL / 8, 256>>>(prompt, ln_g, ln_b, pn);

    // 7. dsc: dw3x3 -> GELU -> pw + residual
    dwconv3x3_kernel<<<TOKALL * CH / 256, 256>>>(pn, dsc_dw, dsc_dwb, tA);
    linear_kernel<<<128, 128>>>(tA, nullptr, nullptr, dsc_pw, dsc_pwb, pn, dsco);

    // 8. bilinear x2 upsample -> output [B,C,128,128]
    upsample_kernel<<<BATCH * 128 * 128 / 4, 256>>>(dsco, outp);

    (void)in_sizes; (void)n_in; (void)out_size;
}